// round 8
// baseline (speedup 1.0000x reference)
#include <cuda_runtime.h>

// Problem constants
#define N_ROWS   1344              // B*C = 64*21
#define R_WIN    32                // windows per row (L/MAX_PL = 1024/32)
#define NWIN     (N_ROWS * R_WIN)  // 43008
#define DM       512               // D_MODEL
#define TGT      4                 // MAX_PL/MIN_PL
#define PE_LEN   128               // R_WIN * TGT
#define MAIN_OUT ((long long)N_ROWS * PE_LEN * DM)  // 88080384
#define CLS_BLOCKS (NWIN / 32)     // 1344 (32 windows per block, 8 lanes each)

typedef unsigned long long u64;

// f32x2 packed helpers (sm_103a FFMA2 — PTX-only form).
__device__ __forceinline__ u64 fma2(u64 a, u64 b, u64 c) {
    u64 d; asm("fma.rn.f32x2 %0, %1, %2, %3;" : "=l"(d) : "l"(a), "l"(b), "l"(c));
    return d;
}
__device__ __forceinline__ u64 mul2(u64 a, u64 b) {
    u64 d; asm("mul.rn.f32x2 %0, %1, %2;" : "=l"(d) : "l"(a), "l"(b));
    return d;
}
__device__ __forceinline__ u64 add2(u64 a, u64 b) {
    u64 d; asm("add.rn.f32x2 %0, %1, %2;" : "=l"(d) : "l"(a), "l"(b));
    return d;
}
__device__ __forceinline__ float hadd2(u64 a) {
    float lo, hi;
    asm("mov.b64 {%0, %1}, %2;" : "=f"(lo), "=f"(hi) : "l"(a));
    return lo + hi;
}

// Scratch (no allocation allowed in kernel_launch)
__device__ unsigned char g_pred[NWIN];

// ---------------------------------------------------------------------------
// Kernel 1: classifier + tail fill.
// 16x more parallel than before: 8 lanes per window (thread = (window, h-octet)),
// shfl_xor reduce over the octet. Grid: 1344 classifier blocks + tail blocks.
// ---------------------------------------------------------------------------
__global__ void __launch_bounds__(256)
pre_kernel(const float* __restrict__ x,
           const float* __restrict__ w1,
           const float* __restrict__ b1,
           const float* __restrict__ w2,
           const float* __restrict__ b2,
           float* __restrict__ out,
           long long tail_start, long long total) {
    int bid = blockIdx.x;
    if (bid >= CLS_BLOCKS) {
        long long i = tail_start + (long long)(bid - CLS_BLOCKS) * 256 + threadIdx.x;
        if (i < total) out[i] = 21.0f;   // reference returns (x_patch, C=21)
        return;
    }

    int tid = threadIdx.x;
    int wl  = tid >> 3;                  // window-in-block 0..31
    int p   = tid & 7;                   // h-octet 0..7
    int w   = bid * 32 + wl;

    const float4* xw = (const float4*)(x + (size_t)w * 32);
    float4 xv[8];
#pragma unroll
    for (int i = 0; i < 8; i++) xv[i] = xw[i];

    float l0 = 0.f, l1 = 0.f, l2 = 0.f;
#pragma unroll
    for (int j = 0; j < 8; j++) {
        int h = p * 8 + j;
        const float4* wr = (const float4*)(w1 + h * 32);
        float a0 = 0.f, a1 = 0.f, a2 = 0.f, a3 = 0.f;
#pragma unroll
        for (int i = 0; i < 8; i++) {
            float4 wv = __ldg(&wr[i]);
            a0 = fmaf(wv.x, xv[i].x, a0);
            a1 = fmaf(wv.y, xv[i].y, a1);
            a2 = fmaf(wv.z, xv[i].z, a2);
            a3 = fmaf(wv.w, xv[i].w, a3);
        }
        float hv = b1[h] + ((a0 + a1) + (a2 + a3));
        hv = fmaxf(hv, 0.0f);
        l0 = fmaf(w2[h], hv, l0);
        l1 = fmaf(w2[64 + h], hv, l1);
        l2 = fmaf(w2[128 + h], hv, l2);
    }
#pragma unroll
    for (int m = 1; m < 8; m <<= 1) {
        l0 += __shfl_xor_sync(0xffffffffu, l0, m);
        l1 += __shfl_xor_sync(0xffffffffu, l1, m);
        l2 += __shfl_xor_sync(0xffffffffu, l2, m);
    }
    if (p == 0) {
        l0 += b2[0]; l1 += b2[1]; l2 += b2[2];
        int pr = 0;
        float mm = l0;
        if (l1 > mm) { mm = l1; pr = 1; }   // strict > = first-max (jnp.argmax)
        if (l2 > mm) { mm = l2; pr = 2; }
        g_pred[w] = (unsigned char)pr;
    }
}

// ---------------------------------------------------------------------------
// Kernel 2: embedding + repeat + PE + store. R7 mapping + PE phase trick:
//   odd d: pe = cos(tD) = sin(tD + pi/2)  -> init (s,c)=(1,0)
//   even d: pe = sin(tD)                  -> init (s,c)=(0,1)
// Per window (base angle = 4wD), with precomputed sin/cos(kD), k=1..4:
//   out_k = fma(s, cK, fma(c, sK, v_k))   -- independent FMAs, PE add folded
//   then advance (s,c) by 4D.
// 11 FMA-class instr/window vs 24 before, no serial 8-FMA chain.
// __launch_bounds__(256,2): guaranteed 2 CTAs/SM, natural regs ~110, no spill.
// ---------------------------------------------------------------------------
__global__ void __launch_bounds__(256, 2)
emb_kernel(const float* __restrict__ x,
           const float* __restrict__ we0,   // [512][8]
           const float* __restrict__ we1,   // [512][16]
           const float* __restrict__ we2,   // [512][32]
           float* __restrict__ out) {
    __shared__ __align__(16) float s_x[R_WIN * 32];   // 4 KB
    __shared__ unsigned char s_pred[R_WIN];

    const int tid  = threadIdx.x;
    const int n    = blockIdx.x >> 1;
    const int dblk = (blockIdx.x & 1) << 8;
    const int d    = dblk + tid;

    // Weight cache as packed pairs.
    u64 w0r[4], w1r[8], w2r[16];
    {
        const ulonglong2* p0 = (const ulonglong2*)(we0 + d * 8);
#pragma unroll
        for (int i = 0; i < 2; i++) { ulonglong2 v = p0[i]; w0r[2*i] = v.x; w0r[2*i+1] = v.y; }
        const ulonglong2* p1 = (const ulonglong2*)(we1 + d * 16);
#pragma unroll
        for (int i = 0; i < 4; i++) { ulonglong2 v = p1[i]; w1r[2*i] = v.x; w1r[2*i+1] = v.y; }
        const ulonglong2* p2 = (const ulonglong2*)(we2 + d * 32);
#pragma unroll
        for (int i = 0; i < 8; i++) { ulonglong2 v = p2[i]; w2r[2*i] = v.x; w2r[2*i+1] = v.y; }
    }

    // Cooperative loads: x row (1024 floats = 256 float4) + 32 preds.
    {
        const float4* xg = (const float4*)(x + (size_t)n * 1024);
        ((float4*)s_x)[tid] = xg[tid];
        if (tid < R_WIN) s_pred[tid] = g_pred[n * R_WIN + tid];
    }

    // PE setup: step sines/cosines for k = 1..4 steps of Delta.
    const float kLn = -9.21034037197618f / (float)DM;   // -ln(10000)/512
    float delta = expf((float)(d & ~1) * kLn);
    float s1, c1;
    sincosf(delta, &s1, &c1);
    float s2 = 2.0f * s1 * c1;
    float c2 = fmaf(c1, c1, -s1 * s1);
    float s3 = fmaf(s1, c2, c1 * s2);
    float c3 = fmaf(c1, c2, -s1 * s2);
    float s4 = 2.0f * s2 * c2;
    float c4 = fmaf(c2, c2, -s2 * s2);
    // Phase-shifted state: odd d computes cos via sin(x + pi/2).
    float s = (d & 1) ? 1.0f : 0.0f;
    float c = (d & 1) ? 0.0f : 1.0f;

    __syncthreads();

    float* o = out + (size_t)n * (PE_LEN * DM) + d;

#pragma unroll 1
    for (int w = 0; w < R_WIN; w++) {
        int pred = s_pred[w];

        const ulonglong2* xq2 = (const ulonglong2*)(s_x + w * 32);
        u64 xv[16];
#pragma unroll
        for (int i = 0; i < 8; i++) { ulonglong2 v = xq2[i]; xv[2*i] = v.x; xv[2*i+1] = v.y; }

        float v0, v1, v2, v3;
        if (pred == 0) {
            // 4 patches of 8 floats; repeat idx = [0,1,2,3]
            float acc[4];
#pragma unroll
            for (int k = 0; k < 4; k++) {
                u64 a = mul2(w0r[0], xv[4*k]);
                a = fma2(w0r[1], xv[4*k+1], a);
                a = fma2(w0r[2], xv[4*k+2], a);
                a = fma2(w0r[3], xv[4*k+3], a);
                acc[k] = hadd2(a);
            }
            v0 = acc[0]; v1 = acc[1]; v2 = acc[2]; v3 = acc[3];
        } else if (pred == 1) {
            // 2 patches of 16 floats; repeat idx = [0,0,0,1]
            u64 a0 = mul2(w1r[0], xv[0]);
            u64 a1 = mul2(w1r[1], xv[1]);
            a0 = fma2(w1r[2], xv[2], a0);
            a1 = fma2(w1r[3], xv[3], a1);
            a0 = fma2(w1r[4], xv[4], a0);
            a1 = fma2(w1r[5], xv[5], a1);
            a0 = fma2(w1r[6], xv[6], a0);
            a1 = fma2(w1r[7], xv[7], a1);
            float a = hadd2(add2(a0, a1));

            u64 b0 = mul2(w1r[0], xv[8]);
            u64 b1 = mul2(w1r[1], xv[9]);
            b0 = fma2(w1r[2], xv[10], b0);
            b1 = fma2(w1r[3], xv[11], b1);
            b0 = fma2(w1r[4], xv[12], b0);
            b1 = fma2(w1r[5], xv[13], b1);
            b0 = fma2(w1r[6], xv[14], b0);
            b1 = fma2(w1r[7], xv[15], b1);
            float b = hadd2(add2(b0, b1));
            v0 = a; v1 = a; v2 = a; v3 = b;
        } else {
            // 1 patch of 32 floats -> replicated 4x
            u64 a0 = mul2(w2r[0], xv[0]);
            u64 a1 = mul2(w2r[1], xv[1]);
            u64 a2 = mul2(w2r[2], xv[2]);
            u64 a3 = mul2(w2r[3], xv[3]);
#pragma unroll
            for (int i = 4; i < 16; i += 4) {
                a0 = fma2(w2r[i],   xv[i],   a0);
                a1 = fma2(w2r[i+1], xv[i+1], a1);
                a2 = fma2(w2r[i+2], xv[i+2], a2);
                a3 = fma2(w2r[i+3], xv[i+3], a3);
            }
            float cc = hadd2(add2(add2(a0, a1), add2(a2, a3)));
            v0 = cc; v1 = cc; v2 = cc; v3 = cc;
        }

        // PE: independent rotations from the window-base angle, add folded.
        o[0 * DM] = v0 + s;
        o[1 * DM] = fmaf(s, c1, fmaf(c, s1, v1));
        o[2 * DM] = fmaf(s, c2, fmaf(c, s2, v2));
        o[3 * DM] = fmaf(s, c3, fmaf(c, s3, v3));
        // Advance base angle by 4*Delta.
        float ns = fmaf(s, c4, c * s4);
        c = fmaf(c, c4, -s * s4);
        s = ns;

        o += TGT * DM;
    }
}

extern "C" void kernel_launch(void* const* d_in, const int* in_sizes, int n_in,
                              void* d_out, int out_size) {
    const float* x   = (const float*)d_in[0];
    const float* w1  = (const float*)d_in[1];
    const float* b1  = (const float*)d_in[2];
    const float* w2  = (const float*)d_in[3];
    const float* b2  = (const float*)d_in[4];
    const float* we0 = (const float*)d_in[5];
    const float* we1 = (const float*)d_in[6];
    const float* we2 = (const float*)d_in[7];
    float* out = (float*)d_out;

    long long total = (long long)out_size;
    long long tail  = (total > MAIN_OUT) ? (total - MAIN_OUT) : 0;
    int tail_blocks = (int)((tail + 255) / 256);

    pre_kernel<<<CLS_BLOCKS + tail_blocks, 256>>>(x, w1, b1, w2, b2,
                                                  out, MAIN_OUT, total);
    emb_kernel<<<N_ROWS * 2, 256>>>(x, we0, we1, we2, out);
}

// round 9
// speedup vs baseline: 1.6649x; 1.6649x over previous
#include <cuda_runtime.h>

// Problem constants
#define N_ROWS   1344              // B*C = 64*21
#define R_WIN    32                // windows per row (L/MAX_PL = 1024/32)
#define NWIN     (N_ROWS * R_WIN)  // 43008
#define DM       512               // D_MODEL
#define TGT      4                 // MAX_PL/MIN_PL
#define PE_LEN   128               // R_WIN * TGT
#define MAIN_OUT ((long long)N_ROWS * PE_LEN * DM)  // 88080384
#define CLS_BLOCKS (NWIN / 128)    // 336 blocks x 128 threads (1 thread/window)

typedef unsigned long long u64;

// f32x2 packed helpers (sm_103a FFMA2 — PTX-only form).
__device__ __forceinline__ u64 fma2(u64 a, u64 b, u64 c) {
    u64 d; asm("fma.rn.f32x2 %0, %1, %2, %3;" : "=l"(d) : "l"(a), "l"(b), "l"(c));
    return d;
}
__device__ __forceinline__ u64 mul2(u64 a, u64 b) {
    u64 d; asm("mul.rn.f32x2 %0, %1, %2;" : "=l"(d) : "l"(a), "l"(b));
    return d;
}
__device__ __forceinline__ u64 add2(u64 a, u64 b) {
    u64 d; asm("add.rn.f32x2 %0, %1, %2;" : "=l"(d) : "l"(a), "l"(b));
    return d;
}
__device__ __forceinline__ float hadd2(u64 a) {
    float lo, hi;
    asm("mov.b64 {%0, %1}, %2;" : "=f"(lo), "=f"(hi) : "l"(a));
    return lo + hi;
}

// Scratch (no allocation allowed in kernel_launch)
__device__ unsigned char g_pred[NWIN];

// ---------------------------------------------------------------------------
// Kernel 1: classifier + tail fill.
// One thread per window (proven converged-weight mapping), but weights are
// staged in SMEM so the 512 inner-loop weight reads are broadcast LDS
// (1 wavefront each, pipelined) instead of L2-latency LDGs.
// 336 blocks x 128 threads (~2.3 blocks/SM).
// ---------------------------------------------------------------------------
__global__ void __launch_bounds__(128)
pre_kernel(const float* __restrict__ x,
           const float* __restrict__ w1,
           const float* __restrict__ b1,
           const float* __restrict__ w2,
           const float* __restrict__ b2,
           float* __restrict__ out,
           long long tail_start, long long total) {
    int bid = blockIdx.x;
    if (bid >= CLS_BLOCKS) {
        long long i = tail_start + (long long)(bid - CLS_BLOCKS) * 128 + threadIdx.x;
        if (i < total) out[i] = 21.0f;   // reference returns (x_patch, C=21)
        return;
    }

    __shared__ __align__(16) float s_w1[64 * 32];   // 8 KB
    __shared__ __align__(16) float s_w2[192];
    __shared__ float s_b1[64];
    __shared__ float s_b2[3];

    const int tid = threadIdx.x;

    // Cooperative coalesced staging.
    {
        const float4* g = (const float4*)w1;
        float4* sm = (float4*)s_w1;
#pragma unroll
        for (int i = 0; i < 4; i++) sm[tid + 128 * i] = g[tid + 128 * i];
        if (tid < 48) ((float4*)s_w2)[tid] = ((const float4*)w2)[tid];
        if (tid < 64) s_b1[tid] = b1[tid];
        if (tid < 3)  s_b2[tid] = b2[tid];
    }
    __syncthreads();

    const int w = bid * 128 + tid;

    // Window in registers.
    const float4* xw = (const float4*)(x + (size_t)w * 32);
    float4 xv[8];
#pragma unroll
    for (int i = 0; i < 8; i++) xv[i] = xw[i];

    float l0 = s_b2[0], l1 = s_b2[1], l2 = s_b2[2];

#pragma unroll 4
    for (int h = 0; h < 64; h++) {
        const float4* wr = (const float4*)(s_w1 + h * 32);   // broadcast LDS
        float a0 = 0.f, a1 = 0.f, a2 = 0.f, a3 = 0.f;
#pragma unroll
        for (int i = 0; i < 8; i++) {
            float4 wv = wr[i];
            a0 = fmaf(wv.x, xv[i].x, a0);
            a1 = fmaf(wv.y, xv[i].y, a1);
            a2 = fmaf(wv.z, xv[i].z, a2);
            a3 = fmaf(wv.w, xv[i].w, a3);
        }
        float hv = s_b1[h] + ((a0 + a1) + (a2 + a3));
        hv = fmaxf(hv, 0.0f);
        l0 = fmaf(s_w2[h], hv, l0);
        l1 = fmaf(s_w2[64 + h], hv, l1);
        l2 = fmaf(s_w2[128 + h], hv, l2);
    }

    int p = 0;
    float m = l0;
    if (l1 > m) { m = l1; p = 1; }   // strict > = first-max (jnp.argmax)
    if (l2 > m) { m = l2; p = 2; }
    g_pred[w] = (unsigned char)p;
}

// ---------------------------------------------------------------------------
// Kernel 2: embedding + repeat + PE + store (R8's best measured version).
// ---------------------------------------------------------------------------
__global__ void __launch_bounds__(256, 2)
emb_kernel(const float* __restrict__ x,
           const float* __restrict__ we0,   // [512][8]
           const float* __restrict__ we1,   // [512][16]
           const float* __restrict__ we2,   // [512][32]
           float* __restrict__ out) {
    __shared__ __align__(16) float s_x[R_WIN * 32];   // 4 KB
    __shared__ unsigned char s_pred[R_WIN];

    const int tid  = threadIdx.x;
    const int n    = blockIdx.x >> 1;
    const int dblk = (blockIdx.x & 1) << 8;
    const int d    = dblk + tid;

    // Weight cache as packed pairs.
    u64 w0r[4], w1r[8], w2r[16];
    {
        const ulonglong2* p0 = (const ulonglong2*)(we0 + d * 8);
#pragma unroll
        for (int i = 0; i < 2; i++) { ulonglong2 v = p0[i]; w0r[2*i] = v.x; w0r[2*i+1] = v.y; }
        const ulonglong2* p1 = (const ulonglong2*)(we1 + d * 16);
#pragma unroll
        for (int i = 0; i < 4; i++) { ulonglong2 v = p1[i]; w1r[2*i] = v.x; w1r[2*i+1] = v.y; }
        const ulonglong2* p2 = (const ulonglong2*)(we2 + d * 32);
#pragma unroll
        for (int i = 0; i < 8; i++) { ulonglong2 v = p2[i]; w2r[2*i] = v.x; w2r[2*i+1] = v.y; }
    }

    // Cooperative loads: x row (1024 floats = 256 float4) + 32 preds.
    {
        const float4* xg = (const float4*)(x + (size_t)n * 1024);
        ((float4*)s_x)[tid] = xg[tid];
        if (tid < R_WIN) s_pred[tid] = g_pred[n * R_WIN + tid];
    }

    // PE setup: step sines/cosines for k = 1..4 steps of Delta.
    const float kLn = -9.21034037197618f / (float)DM;   // -ln(10000)/512
    float delta = expf((float)(d & ~1) * kLn);
    float s1, c1;
    sincosf(delta, &s1, &c1);
    float s2 = 2.0f * s1 * c1;
    float c2 = fmaf(c1, c1, -s1 * s1);
    float s3 = fmaf(s1, c2, c1 * s2);
    float c3 = fmaf(c1, c2, -s1 * s2);
    float s4 = 2.0f * s2 * c2;
    float c4 = fmaf(c2, c2, -s2 * s2);
    // Phase-shifted state: odd d computes cos via sin(x + pi/2).
    float s = (d & 1) ? 1.0f : 0.0f;
    float c = (d & 1) ? 0.0f : 1.0f;

    __syncthreads();

    float* o = out + (size_t)n * (PE_LEN * DM) + d;

#pragma unroll 1
    for (int w = 0; w < R_WIN; w++) {
        int pred = s_pred[w];

        const ulonglong2* xq2 = (const ulonglong2*)(s_x + w * 32);
        u64 xv[16];
#pragma unroll
        for (int i = 0; i < 8; i++) { ulonglong2 v = xq2[i]; xv[2*i] = v.x; xv[2*i+1] = v.y; }

        float v0, v1, v2, v3;
        if (pred == 0) {
            // 4 patches of 8 floats; repeat idx = [0,1,2,3]
            float acc[4];
#pragma unroll
            for (int k = 0; k < 4; k++) {
                u64 a = mul2(w0r[0], xv[4*k]);
                a = fma2(w0r[1], xv[4*k+1], a);
                a = fma2(w0r[2], xv[4*k+2], a);
                a = fma2(w0r[3], xv[4*k+3], a);
                acc[k] = hadd2(a);
            }
            v0 = acc[0]; v1 = acc[1]; v2 = acc[2]; v3 = acc[3];
        } else if (pred == 1) {
            // 2 patches of 16 floats; repeat idx = [0,0,0,1]
            u64 a0 = mul2(w1r[0], xv[0]);
            u64 a1 = mul2(w1r[1], xv[1]);
            a0 = fma2(w1r[2], xv[2], a0);
            a1 = fma2(w1r[3], xv[3], a1);
            a0 = fma2(w1r[4], xv[4], a0);
            a1 = fma2(w1r[5], xv[5], a1);
            a0 = fma2(w1r[6], xv[6], a0);
            a1 = fma2(w1r[7], xv[7], a1);
            float a = hadd2(add2(a0, a1));

            u64 b0 = mul2(w1r[0], xv[8]);
            u64 b1 = mul2(w1r[1], xv[9]);
            b0 = fma2(w1r[2], xv[10], b0);
            b1 = fma2(w1r[3], xv[11], b1);
            b0 = fma2(w1r[4], xv[12], b0);
            b1 = fma2(w1r[5], xv[13], b1);
            b0 = fma2(w1r[6], xv[14], b0);
            b1 = fma2(w1r[7], xv[15], b1);
            float b = hadd2(add2(b0, b1));
            v0 = a; v1 = a; v2 = a; v3 = b;
        } else {
            // 1 patch of 32 floats -> replicated 4x
            u64 a0 = mul2(w2r[0], xv[0]);
            u64 a1 = mul2(w2r[1], xv[1]);
            u64 a2 = mul2(w2r[2], xv[2]);
            u64 a3 = mul2(w2r[3], xv[3]);
#pragma unroll
            for (int i = 4; i < 16; i += 4) {
                a0 = fma2(w2r[i],   xv[i],   a0);
                a1 = fma2(w2r[i+1], xv[i+1], a1);
                a2 = fma2(w2r[i+2], xv[i+2], a2);
                a3 = fma2(w2r[i+3], xv[i+3], a3);
            }
            float cc = hadd2(add2(add2(a0, a1), add2(a2, a3)));
            v0 = cc; v1 = cc; v2 = cc; v3 = cc;
        }

        // PE: independent rotations from the window-base angle, add folded.
        o[0 * DM] = v0 + s;
        o[1 * DM] = fmaf(s, c1, fmaf(c, s1, v1));
        o[2 * DM] = fmaf(s, c2, fmaf(c, s2, v2));
        o[3 * DM] = fmaf(s, c3, fmaf(c, s3, v3));
        // Advance base angle by 4*Delta.
        float ns = fmaf(s, c4, c * s4);
        c = fmaf(c, c4, -s * s4);
        s = ns;

        o += TGT * DM;
    }
}

extern "C" void kernel_launch(void* const* d_in, const int* in_sizes, int n_in,
                              void* d_out, int out_size) {
    const float* x   = (const float*)d_in[0];
    const float* w1  = (const float*)d_in[1];
    const float* b1  = (const float*)d_in[2];
    const float* w2  = (const float*)d_in[3];
    const float* b2  = (const float*)d_in[4];
    const float* we0 = (const float*)d_in[5];
    const float* we1 = (const float*)d_in[6];
    const float* we2 = (const float*)d_in[7];
    float* out = (float*)d_out;

    long long total = (long long)out_size;
    long long tail  = (total > MAIN_OUT) ? (total - MAIN_OUT) : 0;
    int tail_blocks = (int)((tail + 127) / 128);

    pre_kernel<<<CLS_BLOCKS + tail_blocks, 128>>>(x, w1, b1, w2, b2,
                                                  out, MAIN_OUT, total);
    emb_kernel<<<N_ROWS * 2, 256>>>(x, we0, we1, we2, out);
}